// round 10
// baseline (speedup 1.0000x reference)
#include <cuda_runtime.h>
#include <cstdint>

// TopK-magnitude masking per row. x: (4096, 8192) fp32, K = 819.
// out[r,c] = x[r,c] if |x[r,c]| >= (K-th largest |x| in row r) else 0.
//
// One CTA per row, 512 threads. Row lives in REGISTERS (16 stripped 31-bit
// keys + packed signs). 3-pass radix select (11+10+10 bits):
//   pass 1: full sweep, 2048-bin x4-replicated histogram (fused with load)
//   compaction: one warp-scan per thread reserves slots; candidates
//               (key>>20 == d1, typically ~250 of 8192) written to smem,
//               pass-2 histogram fused into the same loop
//   pass 3: candidate-only sweep (~0.5 elems/thread)
// Fallback to full register sweeps if candidates overflow CANDMAX.

#define ROWLEN  8192
#define TPB     512
#define KSEL    819u
#define NW      (TPB / 32)   // 16 warps
#define NREP    4            // pass-1 histogram replicas
#define CANDMAX 1024

// Suffix-scan + digit select over hist[1024] (2 bins/thread).
// Outputs *sh_digit, *sh_k. Ends with __syncthreads.
__device__ __forceinline__ void suffix_select_1024(
    const unsigned* __restrict__ hist, unsigned k,
    int t, int lane, int wid,
    unsigned* wsum, unsigned* wtail,
    unsigned* sh_digit, unsigned* sh_k)
{
    const int base = t * 2;
    unsigned loc[2];
    unsigned s = 0u;
#pragma unroll
    for (int j = 1; j >= 0; j--) { s += hist[base + j]; loc[j] = s; }
    unsigned p = s;
#pragma unroll
    for (int off = 1; off < 32; off <<= 1) {
        unsigned n = __shfl_down_sync(0xFFFFFFFFu, p, off);
        if (lane < 32 - off) p += n;
    }
    if (lane == 0) wsum[wid] = p;
    __syncthreads();
    if (t < NW) {
        unsigned q = wsum[t];
        unsigned r = q;
#pragma unroll
        for (int off = 1; off < NW; off <<= 1) {
            unsigned n = __shfl_down_sync(0x0000FFFFu, r, off);
            if (t < NW - off) r += n;
        }
        wtail[t] = r - q;
    }
    __syncthreads();
    unsigned beyond = (p - s) + wtail[wid];
#pragma unroll
    for (int j = 0; j < 2; j++) {
        unsigned incl = loc[j] + beyond;
        unsigned cnt  = loc[j] - ((j < 1) ? loc[j + 1] : 0u);
        unsigned gt   = incl - cnt;
        if (incl >= k && gt < k) { *sh_digit = (unsigned)(base + j); *sh_k = k - gt; }
    }
    __syncthreads();
}

__global__ __launch_bounds__(TPB, 3)
void topk_mask_kernel(const float* __restrict__ x, float* __restrict__ out) {
    __shared__ unsigned       hist[NREP * 2048];   // 32 KB (first 1024 reused for pass 3)
    __shared__ unsigned       hist2[1024];         // 4 KB (pass 2)
    __shared__ unsigned       cand_key[CANDMAX];   // 4 KB
    __shared__ unsigned short cand_pos[CANDMAX];   // 2 KB
    __shared__ unsigned       wsum[NW];
    __shared__ unsigned       wtail[NW];
    __shared__ unsigned       sh_digit, sh_k, sh_cnt, ccnt;

    const int t    = threadIdx.x;
    const int lane = t & 31;
    const int wid  = t >> 5;
    const size_t row_off = (size_t)blockIdx.x * ROWLEN;
    const uint4* __restrict__ px = reinterpret_cast<const uint4*>(x + row_off);
    uint4*       __restrict__ po = reinterpret_cast<uint4*>(out + row_off);

    // ---- zero histograms ----
    {
        uint4 z = make_uint4(0u, 0u, 0u, 0u);
        uint4* h4 = reinterpret_cast<uint4*>(hist);
#pragma unroll
        for (int i = 0; i < NREP; i++) h4[t + i * TPB] = z;
        reinterpret_cast<uint2*>(hist2)[t] = make_uint2(0u, 0u);
        if (t == 0) ccnt = 0u;
    }
    __syncthreads();

    // ---- sweep 1: load -> register keys + signs; pass-1 histogram ----
    unsigned key[16];
    unsigned signs = 0u;
    unsigned* hrep = &hist[(wid & (NREP - 1)) * 2048];
#pragma unroll
    for (int i = 0; i < 4; i++) {
        uint4 a = px[t + i * TPB];
        const unsigned b[4] = {a.x, a.y, a.z, a.w};
#pragma unroll
        for (int c = 0; c < 4; c++) {
            const int idx = i * 4 + c;
            unsigned kk = b[c] & 0x7FFFFFFFu;
            key[idx] = kk;
            signs |= (b[c] >> 31) << idx;
            atomicAdd(&hrep[kk >> 20], 1u);
        }
    }
    __syncthreads();

    unsigned k = KSEL;
    unsigned d1, d2;

    // ---- select 1: 2048 bins, replica sum, 4 bins/thread ----
    {
        const int base = t * 4;
        unsigned loc[4];
        unsigned s = 0u;
#pragma unroll
        for (int j = 3; j >= 0; j--) {
            unsigned cnt = 0u;
#pragma unroll
            for (int r = 0; r < NREP; r++) cnt += hist[r * 2048 + base + j];
            s += cnt; loc[j] = s;
        }
        unsigned p = s;
#pragma unroll
        for (int off = 1; off < 32; off <<= 1) {
            unsigned n = __shfl_down_sync(0xFFFFFFFFu, p, off);
            if (lane < 32 - off) p += n;
        }
        if (lane == 0) wsum[wid] = p;
        __syncthreads();
        if (t < NW) {
            unsigned q = wsum[t];
            unsigned r = q;
#pragma unroll
            for (int off = 1; off < NW; off <<= 1) {
                unsigned n = __shfl_down_sync(0x0000FFFFu, r, off);
                if (t < NW - off) r += n;
            }
            wtail[t] = r - q;
        }
        __syncthreads();
        unsigned beyond = (p - s) + wtail[wid];
#pragma unroll
        for (int j = 0; j < 4; j++) {
            unsigned incl = loc[j] + beyond;
            unsigned cnt  = loc[j] - ((j < 3) ? loc[j + 1] : 0u);
            unsigned gt   = incl - cnt;
            if (incl >= k && gt < k) {
                sh_digit = (unsigned)(base + j); sh_k = k - gt; sh_cnt = cnt;
            }
        }
        __syncthreads();
        d1 = sh_digit; k = sh_k;
    }
    const unsigned C    = sh_cnt;          // candidates (digit == d1)
    const bool     fits = (C <= CANDMAX);  // CTA-uniform

    // ---- compaction + fused pass-2 histogram; zero hist[0..1023] for pass 3 ----
    reinterpret_cast<uint2*>(hist)[t] = make_uint2(0u, 0u);
    if (fits) {
        unsigned mycnt = 0u;
#pragma unroll
        for (int idx = 0; idx < 16; idx++) mycnt += ((key[idx] >> 20) == d1);
        unsigned incl = mycnt;               // warp inclusive scan
#pragma unroll
        for (int off = 1; off < 32; off <<= 1) {
            unsigned n = __shfl_up_sync(0xFFFFFFFFu, incl, off);
            if (lane >= off) incl += n;
        }
        unsigned wtot = __shfl_sync(0xFFFFFFFFu, incl, 31);
        unsigned wbase = 0u;
        if (lane == 31) wbase = atomicAdd(&ccnt, wtot);   // one atomic per warp
        wbase = __shfl_sync(0xFFFFFFFFu, wbase, 31);
        unsigned pos = wbase + incl - mycnt;
#pragma unroll
        for (int i = 0; i < 4; i++) {
#pragma unroll
            for (int c = 0; c < 4; c++) {
                const int idx = i * 4 + c;
                unsigned kk = key[idx];
                if ((kk >> 20) == d1) {
                    cand_key[pos] = kk;
                    cand_pos[pos] = (unsigned short)(4 * (t + i * TPB) + c);
                    atomicAdd(&hist2[(kk >> 10) & 0x3FFu], 1u);
                    pos++;
                }
            }
        }
    } else {
        // fallback: full register sweep for pass-2 histogram
#pragma unroll
        for (int idx = 0; idx < 16; idx++) {
            unsigned kk = key[idx];
            if ((kk >> 20) == d1)
                atomicAdd(&hist2[(kk >> 10) & 0x3FFu], 1u);
        }
    }
    __syncthreads();

    // ---- select 2 ----
    suffix_select_1024(hist2, k, t, lane, wid, wsum, wtail, &sh_digit, &sh_k);
    d2 = sh_digit; k = sh_k;
    const unsigned pref21 = (d1 << 10) | d2;   // == key >> 10 for survivors

    // ---- pass 3 histogram ----
    if (fits) {
        for (unsigned j = t; j < C; j += TPB) {
            unsigned kk = cand_key[j];
            if ((kk >> 10) == pref21)
                atomicAdd(&hist[kk & 0x3FFu], 1u);
        }
    } else {
#pragma unroll
        for (int idx = 0; idx < 16; idx++) {
            unsigned kk = key[idx];
            if ((kk >> 10) == pref21)
                atomicAdd(&hist[kk & 0x3FFu], 1u);
        }
    }
    __syncthreads();

    // ---- select 3 ----
    suffix_select_1024(hist, k, t, lane, wid, wsum, wtail, &sh_digit, &sh_k);
    const unsigned T = (pref21 << 10) | sh_digit;   // K-th largest |x| pattern

    // ---- epilogue: reconstruct value from key+sign, masked float4 store ----
#pragma unroll
    for (int i = 0; i < 4; i++) {
        unsigned o[4];
#pragma unroll
        for (int c = 0; c < 4; c++) {
            const int idx = i * 4 + c;
            unsigned kk = key[idx];
            unsigned bits = kk | (((signs >> idx) & 1u) << 31);
            o[c] = (kk < T) ? 0u : bits;
        }
        po[t + i * TPB] = make_uint4(o[0], o[1], o[2], o[3]);
    }
}

extern "C" void kernel_launch(void* const* d_in, const int* in_sizes, int n_in,
                              void* d_out, int out_size) {
    const float* x = (const float*)d_in[0];
    float* out = (float*)d_out;
    const int rows = in_sizes[0] / ROWLEN;   // 4096
    topk_mask_kernel<<<rows, TPB>>>(x, out);
}

// round 11
// speedup vs baseline: 1.0257x; 1.0257x over previous
#include <cuda_runtime.h>
#include <cstdint>

// TopK-magnitude masking per row. x: (4096, 8192) fp32, K = 819.
// out[r,c] = x[r,c] if |x[r,c]| >= (K-th largest |x| in row r) else 0.
//
// One CTA per row, 512 threads, row staged in SMEM, <=32 regs -> 4 CTAs/SM.
// 3-pass radix select (11+10+10 bits) on bits(|x|), but only TWO full-row
// sweeps total:
//   sweep 1: LDG -> STS + pass-1 histogram (2048 bins)
//   sweep 2: LDS -> FINAL STG for decided elements + pass-2 histogram +
//            ballot/popc compaction of candidates (dig==d1, ~250/row) into
//            per-warp segments (no cross-warp atomics)
// Pass 3 + fixup touch only the compacted candidates. Fallback to full-row
// sweeps if any warp segment overflows (CTA-uniform, never for Gaussian).

#define ROWLEN 8192
#define TPB    512
#define KSEL   819u
#define NW     (TPB / 32)   // 16 warps
#define CAP    80           // candidate slots per warp (expected ~16)

// Suffix-scan + digit select over h[NB]; outputs *sh_digit/*sh_k.
// Ends with __syncthreads.
template <int NB>
__device__ __forceinline__ void suffix_select(
    const unsigned* __restrict__ h, unsigned k,
    int t, int lane, int wid,
    unsigned* wsum, unsigned* wtail,
    volatile unsigned* sh_digit, volatile unsigned* sh_k)
{
    constexpr int B = NB / TPB;           // 4 (2048 bins) or 2 (1024 bins)
    const int base = t * B;
    unsigned loc[B];
    unsigned s = 0u;
#pragma unroll
    for (int j = B - 1; j >= 0; j--) { s += h[base + j]; loc[j] = s; }
    unsigned p = s;                        // warp suffix scan of chunk totals
#pragma unroll
    for (int off = 1; off < 32; off <<= 1) {
        unsigned n = __shfl_down_sync(0xFFFFFFFFu, p, off);
        if (lane < 32 - off) p += n;
    }
    if (lane == 0) wsum[wid] = p;
    __syncthreads();
    if (t < NW) {
        unsigned q = wsum[t];
        unsigned r = q;
#pragma unroll
        for (int off = 1; off < NW; off <<= 1) {
            unsigned n = __shfl_down_sync(0x0000FFFFu, r, off);
            if (t < NW - off) r += n;
        }
        wtail[t] = r - q;                  // total of warps AFTER warp t
    }
    __syncthreads();
    unsigned beyond = (p - s) + wtail[wid];
#pragma unroll
    for (int j = 0; j < B; j++) {
        unsigned incl = loc[j] + beyond;                          // count(>=d)
        unsigned cnt  = loc[j] - ((j < B - 1) ? loc[j + 1] : 0u); // hist[d]
        unsigned gt   = incl - cnt;                               // count(>d)
        if (incl >= k && gt < k) { *sh_digit = (unsigned)(base + j); *sh_k = k - gt; }
    }
    __syncthreads();
}

__global__ __launch_bounds__(TPB, 4)
void topk_mask_kernel(const float* __restrict__ x, float* __restrict__ out) {
    __shared__ unsigned       row[ROWLEN];      // 32 KB (keys+signs as raw bits)
    __shared__ unsigned       hist[2048];       // 8 KB, reused across passes
    __shared__ unsigned       ck[NW * CAP];     // 5 KB candidate keys
    __shared__ unsigned short cp[NW * CAP];     // 2.5 KB candidate positions
    __shared__ unsigned       wsum[NW], wtail[NW], wcnt[NW];
    __shared__ unsigned       sh_digit, sh_k, sh_flag;

    const int t    = threadIdx.x;
    const int lane = t & 31;
    const int wid  = t >> 5;
    const unsigned mylt = (1u << lane) - 1u;
    const size_t row_off = (size_t)blockIdx.x * ROWLEN;
    const uint4* __restrict__ px   = reinterpret_cast<const uint4*>(x + row_off);
    uint4*       __restrict__ po   = reinterpret_cast<uint4*>(out + row_off);
    float*       __restrict__ pout = out + row_off;
    uint4*                    prow = reinterpret_cast<uint4*>(row);

    // ---- zero pass-1 histogram ----
    reinterpret_cast<uint4*>(hist)[t] = make_uint4(0u, 0u, 0u, 0u);
    if (t == 0) sh_flag = 0u;
    __syncthreads();

    // ---- sweep 1: global load -> smem stage + pass-1 histogram (key>>20) ----
#pragma unroll
    for (int i = 0; i < 4; i++) {
        uint4 a = px[t + i * TPB];
        prow[t + i * TPB] = a;
        atomicAdd(&hist[(a.x & 0x7FFFFFFFu) >> 20], 1u);
        atomicAdd(&hist[(a.y & 0x7FFFFFFFu) >> 20], 1u);
        atomicAdd(&hist[(a.z & 0x7FFFFFFFu) >> 20], 1u);
        atomicAdd(&hist[(a.w & 0x7FFFFFFFu) >> 20], 1u);
    }
    __syncthreads();

    unsigned k = KSEL;
    suffix_select<2048>(hist, k, t, lane, wid, wsum, wtail, &sh_digit, &sh_k);
    const unsigned d1 = sh_digit; k = sh_k;

    // ---- zero hist for pass 2 ([0,1024)) and pass 3 ([1024,2048)) ----
    reinterpret_cast<uint4*>(hist)[t] = make_uint4(0u, 0u, 0u, 0u);
    __syncthreads();

    // ---- sweep 2 (the ONLY full LDS sweep): final store + pass-2 hist +
    //      per-warp ballot compaction of candidates ----
    unsigned wcount = 0u;
#pragma unroll
    for (int i = 0; i < 4; i++) {
        uint4 a = prow[t + i * TPB];
        const unsigned b[4] = {a.x, a.y, a.z, a.w};
        unsigned o[4];
#pragma unroll
        for (int c = 0; c < 4; c++) {
            unsigned kk  = b[c] & 0x7FFFFFFFu;
            unsigned dig = kk >> 20;
            // decided: dig<d1 -> 0, dig>d1 -> keep; dig==d1 provisional keep
            o[c] = (dig < d1) ? 0u : b[c];
            bool isc = (dig == d1);
            unsigned m = __ballot_sync(0xFFFFFFFFu, isc);
            if (isc) {
                unsigned idx = wcount + (unsigned)__popc(m & mylt);
                if (idx < CAP) {
                    ck[wid * CAP + idx] = kk;
                    cp[wid * CAP + idx] = (unsigned short)(4 * (t + i * TPB) + c);
                    atomicAdd(&hist[(kk >> 10) & 0x3FFu], 1u);
                }
            }
            wcount += (unsigned)__popc(m);
        }
        po[t + i * TPB] = make_uint4(o[0], o[1], o[2], o[3]);
    }
    if (lane == 0) wcnt[wid] = wcount;
    __syncthreads();
    if (t < NW && wcnt[t] > CAP) sh_flag = 1u;
    __syncthreads();
    const bool flag = (sh_flag != 0u);     // CTA-uniform overflow fallback

    if (flag) {
        // recount pass-2 histogram from scratch (compaction was lossy)
        reinterpret_cast<uint2*>(hist)[t] = make_uint2(0u, 0u);  // [0,1024)
        __syncthreads();
#pragma unroll
        for (int i = 0; i < 4; i++) {
            uint4 a = prow[t + i * TPB];
            const unsigned b[4] = {a.x, a.y, a.z, a.w};
#pragma unroll
            for (int c = 0; c < 4; c++) {
                unsigned kk = b[c] & 0x7FFFFFFFu;
                if ((kk >> 20) == d1)
                    atomicAdd(&hist[(kk >> 10) & 0x3FFu], 1u);
            }
        }
        __syncthreads();
    }

    // ---- select 2 (bits [10,20)) over hist[0..1023] ----
    suffix_select<1024>(hist, k, t, lane, wid, wsum, wtail, &sh_digit, &sh_k);
    const unsigned d2 = sh_digit; k = sh_k;
    const unsigned pref21 = (d1 << 10) | d2;   // == key >> 10 for survivors

    // ---- pass 3 histogram (bits [0,10)) into hist[1024..2047] ----
    unsigned* hist3 = hist + 1024;
    if (!flag) {
#pragma unroll
        for (int seg = 0; seg < NW; seg++) {
            if ((unsigned)t < wcnt[seg]) {
                unsigned kk = ck[seg * CAP + t];
                if ((kk >> 10) == pref21)
                    atomicAdd(&hist3[kk & 0x3FFu], 1u);
            }
        }
    } else {
#pragma unroll
        for (int i = 0; i < 4; i++) {
            uint4 a = prow[t + i * TPB];
            const unsigned b[4] = {a.x, a.y, a.z, a.w};
#pragma unroll
            for (int c = 0; c < 4; c++) {
                unsigned kk = b[c] & 0x7FFFFFFFu;
                if ((kk >> 10) == pref21)
                    atomicAdd(&hist3[kk & 0x3FFu], 1u);
            }
        }
    }
    __syncthreads();

    // ---- select 3 ----
    suffix_select<1024>(hist3, k, t, lane, wid, wsum, wtail, &sh_digit, &sh_k);
    const unsigned T = (pref21 << 10) | sh_digit;   // K-th largest |x| pattern

    // ---- fixup: zero provisional candidates below T (scattered 4B stores) ----
    if (!flag) {
#pragma unroll
        for (int seg = 0; seg < NW; seg++) {
            if ((unsigned)t < wcnt[seg]) {
                if (ck[seg * CAP + t] < T)
                    pout[cp[seg * CAP + t]] = 0.0f;
            }
        }
    } else {
#pragma unroll
        for (int i = 0; i < 4; i++) {
            uint4 a = prow[t + i * TPB];
            const unsigned b[4] = {a.x, a.y, a.z, a.w};
#pragma unroll
            for (int c = 0; c < 4; c++) {
                unsigned kk = b[c] & 0x7FFFFFFFu;
                if ((kk >> 20) == d1 && kk < T)
                    pout[4 * (t + i * TPB) + c] = 0.0f;
            }
        }
    }
}

extern "C" void kernel_launch(void* const* d_in, const int* in_sizes, int n_in,
                              void* d_out, int out_size) {
    const float* x = (const float*)d_in[0];
    float* out = (float*)d_out;
    const int rows = in_sizes[0] / ROWLEN;   // 4096
    topk_mask_kernel<<<rows, TPB>>>(x, out);
}